// round 16
// baseline (speedup 1.0000x reference)
#include <cuda_runtime.h>
#include <math.h>
#include <stdint.h>

#define NN     50000
#define EE     400000
#define WIDTH  256          // H(4) * padded D(64)
#define HEADS  4
#define SLOPEV 0.2f

// ---------------- static scratch (no allocations allowed) ----------------
__device__ __align__(256) float g_hs [NN * WIDTH];
__device__ __align__(256) float g_hd [NN * WIDTH];
__device__ __align__(256) float g_res[NN * WIDTH];
__device__ __align__(256) float g_xa [NN * WIDTH];
__device__ __align__(256) float g_xb [NN * WIDTH];
__device__ int   g_cnt[NN];
__device__ int   g_rowptr[NN + 1];
__device__ int   g_wp [NN];
__device__ int   g_csrsrc[EE];
// concatenated, tf32-rounded, COLUMN-PERMUTED weights + (logical-order) biases
__device__ float g_wcat0[128 * 768];
__device__ float g_bcat0[768];
__device__ float g_wcat1[256 * 512];
__device__ float g_bcat1[512];
__device__ float g_wcat2[256 * 480];
__device__ float g_bcat2[480];

__device__ __forceinline__ float rna_tf32(float x) {
    float r;
    asm("cvt.rna.tf32.f32 %0, %1;" : "=f"(r) : "f"(x));
    return r;
}

// ---------------- CSR build ----------------
__global__ void k_zero_cnt(int* __restrict__ cnt) {
    int i = blockIdx.x * blockDim.x + threadIdx.x;
    if (i < NN) cnt[i] = 0;
}

__global__ void k_count(const int* __restrict__ dst, int* __restrict__ cnt) {
    int e = blockIdx.x * blockDim.x + threadIdx.x;
    if (e < EE) atomicAdd(&cnt[dst[e]], 1);
}

__global__ void k_scan(const int* __restrict__ cnt,
                       int* __restrict__ rowptr, int* __restrict__ wp) {
    __shared__ int sums[1024];
    const int t = threadIdx.x;
    const int CH = (NN + 1023) / 1024;
    int start = t * CH;
    int end   = start + CH; if (end > NN) end = NN;
    int s = 0;
    for (int i = start; i < end; i++) s += cnt[i];
    sums[t] = s;
    __syncthreads();
    for (int off = 1; off < 1024; off <<= 1) {
        int v = (t >= off) ? sums[t - off] : 0;
        __syncthreads();
        sums[t] += v;
        __syncthreads();
    }
    int run = (t == 0) ? 0 : sums[t - 1];
    for (int i = start; i < end; i++) {
        rowptr[i] = run;
        wp[i]     = run;
        run += cnt[i];
    }
    if (t == 1023) rowptr[NN] = run;
}

__global__ void k_scatter(const int* __restrict__ src, const int* __restrict__ dst,
                          int* __restrict__ wp, int* __restrict__ csrsrc) {
    int e = blockIdx.x * blockDim.x + threadIdx.x;
    if (e < EE) {
        int pos = atomicAdd(&wp[dst[e]], 1);
        csrsrc[pos] = src[e];
    }
}

// ---------------- weight concat + tf32 rounding + column permutation ----------------
// Storage col p (within 32-block): g = (p&31)>>2, ni = p&3  ->  logical col (p&~31) | (ni*8+g)
// This makes B mma-fragment loads vectorizable as LDS.128 in k_mma.
__global__ void k_catcvt(const float* __restrict__ wa, const float* __restrict__ wb,
                         const float* __restrict__ wc,
                         const float* __restrict__ ba, const float* __restrict__ bb,
                         const float* __restrict__ bc,
                         float* __restrict__ wcat, float* __restrict__ bcat,
                         int K, int Nw, int np) {
    int total = K * Nw * np;
    int i = blockIdx.x * blockDim.x + threadIdx.x;
    if (i < total) {
        int Ntot = Nw * np;
        int k = i / Ntot;
        int p = i - k * Ntot;                 // storage column
        int p5 = p & 31;
        int g  = p5 >> 2;
        int ni = p5 & 3;
        int c  = (p & ~31) | (ni * 8 + g);    // logical column
        int part = c / Nw;
        int j = c - part * Nw;
        const float* w = (part == 0) ? wa : ((part == 1) ? wb : wc);
        wcat[i] = rna_tf32(w[k * Nw + j]);
    } else if (i < total + np * Nw) {
        int t = i - total;                    // bias kept in LOGICAL order
        int part = t / Nw;
        int j = t - part * Nw;
        const float* b = (part == 0) ? ba : ((part == 1) ? bb : bc);
        bcat[t] = b[j];
    }
}

// ---------------- tf32 tensor-core GEMM (3-stage cp.async + LDSM A + LDS.128 B) ----
#define BM 128
#define BN 128
#define BKK 32
#define SAK 36
#define SBN 136     // SBN/4 == 34 ≡ 2 (mod 8): conflict-free LDS.128 B-fragment phases
#define NSTAGE 3
#define STAGE_FLOATS (BM * SAK + BKK * SBN)     // 4608 + 4352 = 8960
#define CSTRIDE 132

#define CP_ASYNC16(dst, src, sz) \
    asm volatile("cp.async.cg.shared.global [%0], [%1], 16, %2;\n" \
                 :: "r"(dst), "l"(src), "r"(sz))

__device__ __forceinline__ void mma_tf32(float* c, const uint32_t* a, const uint32_t* b) {
    asm volatile(
        "mma.sync.aligned.m16n8k8.row.col.f32.tf32.tf32.f32 "
        "{%0,%1,%2,%3}, {%4,%5,%6,%7}, {%8,%9}, {%0,%1,%2,%3};\n"
        : "+f"(c[0]), "+f"(c[1]), "+f"(c[2]), "+f"(c[3])
        : "r"(a[0]), "r"(a[1]), "r"(a[2]), "r"(a[3]), "r"(b[0]), "r"(b[1]));
}

__global__ __launch_bounds__(256, 2)
void k_mma(const float* __restrict__ A, const float* __restrict__ Bcat,
           const float* __restrict__ bcat,
           float* __restrict__ C0, float* __restrict__ C1, float* __restrict__ C2,
           int M, int K, int Ntot, int Nw, int remap) {
    extern __shared__ float smem[];

    const int tid  = threadIdx.x;
    const int warp = tid >> 5;
    const int lane = tid & 31;
    const int gid  = lane >> 2;
    const int tig  = lane & 3;
    const int warpM = (warp >> 2) * 64;
    const int warpN = (warp & 3) * 32;
    const int bm = blockIdx.y * BM;
    const int bn = blockIdx.x * BN;
    const int lmRow  = lane & 15;
    const int lmCol4 = ((lane >> 4) & 1) * 4;

    float acc[4][4][4];
    #pragma unroll
    for (int mi = 0; mi < 4; mi++)
        #pragma unroll
        for (int ni = 0; ni < 4; ni++)
            #pragma unroll
            for (int r = 0; r < 4; r++) acc[mi][ni][r] = 0.f;

    const int T = K / BKK;

    auto load_stage = [&](int buf, int k0) {
        float* Asm = smem + buf * STAGE_FLOATS;
        float* Bsm = Asm + BM * SAK;
        #pragma unroll
        for (int i = 0; i < 4; i++) {
            int idx = tid + i * 256;
            int row = idx >> 3;
            int c4  = (idx & 7) * 4;
            int gr  = bm + row;
            int grc = (gr < M) ? gr : (M - 1);
            const float* gp = A + (size_t)grc * K + k0 + c4;
            uint32_t sp = (uint32_t)__cvta_generic_to_shared(Asm + row * SAK + c4);
            CP_ASYNC16(sp, gp, (gr < M) ? 16 : 0);
        }
        #pragma unroll
        for (int i = 0; i < 4; i++) {
            int idx = tid + i * 256;
            int k   = idx >> 5;
            int c4  = (idx & 31) * 4;          // storage (permuted) column
            int gc  = bn + c4;
            int gcc = (gc < Ntot) ? gc : 0;
            const float* gp = Bcat + (size_t)(k0 + k) * Ntot + gcc;
            uint32_t sp = (uint32_t)__cvta_generic_to_shared(Bsm + k * SBN + c4);
            CP_ASYNC16(sp, gp, (gc < Ntot) ? 16 : 0);
        }
        asm volatile("cp.async.commit_group;\n");
    };

    load_stage(0, 0);
    if (T > 1) load_stage(1, BKK);

    int buf = 0;
    for (int t = 0; t < T; t++) {
        if (t + 2 < T) {
            int nb = (buf + 2 >= NSTAGE) ? (buf + 2 - NSTAGE) : (buf + 2);
            load_stage(nb, (t + 2) * BKK);
            asm volatile("cp.async.wait_group 2;\n");
        } else if (t + 1 < T) {
            asm volatile("cp.async.wait_group 1;\n");
        } else {
            asm volatile("cp.async.wait_group 0;\n");
        }
        __syncthreads();

        const float* As = smem + buf * STAGE_FLOATS;
        const float* Bs = As + BM * SAK;
        const uint32_t sA = (uint32_t)__cvta_generic_to_shared(As);

        #pragma unroll
        for (int ks = 0; ks < 4; ks++) {
            const int kk = ks * 8;
            uint32_t a[4][4];
            #pragma unroll
            for (int mi = 0; mi < 4; mi++) {
                uint32_t addr = sA + (uint32_t)(((warpM + mi * 16 + lmRow) * SAK + kk + lmCol4) * 4);
                asm volatile(
                    "ldmatrix.sync.aligned.m8n8.x4.shared.b16 {%0,%1,%2,%3}, [%4];\n"
                    : "=r"(a[mi][0]), "=r"(a[mi][1]), "=r"(a[mi][2]), "=r"(a[mi][3])
                    : "r"(addr));
            }
            #pragma unroll
            for (int mi = 0; mi < 4; mi++)
                #pragma unroll
                for (int q = 0; q < 4; q++)
                    a[mi][q] = __float_as_uint(rna_tf32(__uint_as_float(a[mi][q])));
            // B fragments: permuted storage makes all 4 ni's b0 (and b1) contiguous
            uint32_t b[4][2];
            {
                const float4 bv0 = *(const float4*)&Bs[(kk + tig) * SBN + warpN + gid * 4];
                const float4 bv1 = *(const float4*)&Bs[(kk + tig + 4) * SBN + warpN + gid * 4];
                b[0][0] = __float_as_uint(bv0.x); b[1][0] = __float_as_uint(bv0.y);
                b[2][0] = __float_as_uint(bv0.z); b[3][0] = __float_as_uint(bv0.w);
                b[0][1] = __float_as_uint(bv1.x); b[1][1] = __float_as_uint(bv1.y);
                b[2][1] = __float_as_uint(bv1.z); b[3][1] = __float_as_uint(bv1.w);
            }
            #pragma unroll
            for (int mi = 0; mi < 4; mi++)
                #pragma unroll
                for (int ni = 0; ni < 4; ni++)
                    mma_tf32(acc[mi][ni], a[mi], b[ni]);
        }
        __syncthreads();
        buf = (buf + 1 == NSTAGE) ? 0 : (buf + 1);
    }

    // ---- coalesced epilogue: stage accumulators (LOGICAL columns) in smem ----
    float* Cs = smem;
    #pragma unroll
    for (int mi = 0; mi < 4; mi++)
        #pragma unroll
        for (int ni = 0; ni < 4; ni++)
            #pragma unroll
            for (int half = 0; half < 2; half++) {
                int r  = warpM + mi * 16 + gid + half * 8;
                int cb = warpN + ni * 8 + tig * 2;
                Cs[r * CSTRIDE + cb]     = acc[mi][ni][half * 2 + 0];
                Cs[r * CSTRIDE + cb + 1] = acc[mi][ni][half * 2 + 1];
            }
    __syncthreads();

    {
        const int cg = bn + lane * 4;       // logical global col of this lane's 4-chunk
        if (cg < Ntot) {
            int part = cg / Nw;
            int j = cg - part * Nw;
            int cc = remap ? ((j / 40) * 64 + (j % 40)) : j;
            float* P = (part == 0) ? C0 : ((part == 1) ? C1 : C2);
            const float4 b4 = *(const float4*)&bcat[cg];
            #pragma unroll 4
            for (int i = 0; i < 16; i++) {
                int r  = warp * 16 + i;
                int gr = bm + r;
                if (gr >= M) break;
                float4 v = *(float4*)&Cs[r * CSTRIDE + lane * 4];
                v.x += b4.x; v.y += b4.y; v.z += b4.z; v.w += b4.w;
                *(float4*)&P[(size_t)gr * WIDTH + cc] = v;
            }
        }
    }
}

// ---------------- per-dst-node edge softmax + aggregation (1 warp / node) ----------
__global__ __launch_bounds__(256)
void k_edge(const float* __restrict__ hs, const float* __restrict__ hd,
            const float* __restrict__ res, const float* __restrict__ attn,
            int realD,
            const int* __restrict__ rowptr, const int* __restrict__ csrsrc,
            float* __restrict__ xout, float* __restrict__ meanout) {
    const int warp = (blockIdx.x * blockDim.x + threadIdx.x) >> 5;
    const int lane = threadIdx.x & 31;
    if (warp >= NN) return;
    const int n = warp;
    const int base = n * WIDTH + lane * 8;
    const int h  = lane >> 3;
    const int d0 = (lane * 8) & 63;

    float4 hq0 = *(const float4*)(hd + base);
    float4 hq1 = *(const float4*)(hd + base + 4);
    float hdv[8] = {hq0.x, hq0.y, hq0.z, hq0.w, hq1.x, hq1.y, hq1.z, hq1.w};

    float av[8];
    #pragma unroll
    for (int j = 0; j < 8; j++) {
        int d = d0 + j;
        av[j] = (d < realD) ? attn[h * realD + d] : 0.f;
    }

    float acc[8];
    #pragma unroll
    for (int j = 0; j < 8; j++) acc[j] = 0.f;
    float m = -INFINITY, s = 0.f;

    auto proc = [&](float4 v0, float4 v1) {
        float hsv[8] = {v0.x, v0.y, v0.z, v0.w, v1.x, v1.y, v1.z, v1.w};
        float ph = 0.f;
        #pragma unroll
        for (int j = 0; j < 8; j++) {
            float t = hsv[j] + hdv[j];
            t = (t > 0.f) ? t : SLOPEV * t;
            ph = fmaf(t, av[j], ph);
        }
        ph += __shfl_xor_sync(0xffffffffu, ph, 1);
        ph += __shfl_xor_sync(0xffffffffu, ph, 2);
        ph += __shfl_xor_sync(0xffffffffu, ph, 4);
        float mn = fmaxf(m, ph);
        float sc = __expf(m - mn);
        float w  = __expf(ph - mn);
        s = s * sc + w;
        m = mn;
        #pragma unroll
        for (int j = 0; j < 8; j++)
            acc[j] = fmaf(acc[j], sc, w * hsv[j]);
    };

    const int e0 = rowptr[n], e1 = rowptr[n + 1];
    int e = e0;
    for (; e + 4 <= e1; e += 4) {
        float4 v[8];
        #pragma unroll
        for (int u = 0; u < 4; u++) {
            const float4* p = (const float4*)(hs + (size_t)csrsrc[e + u] * WIDTH + lane * 8);
            v[2 * u]     = p[0];
            v[2 * u + 1] = p[1];
        }
        #pragma unroll
        for (int u = 0; u < 4; u++) proc(v[2 * u], v[2 * u + 1]);
    }
    for (; e < e1; e++) {
        const float4* p = (const float4*)(hs + (size_t)csrsrc[e] * WIDTH + lane * 8);
        proc(p[0], p[1]);
    }

    const float inv = (e1 > e0) ? (1.f / s) : 0.f;
    float4 r0 = *(const float4*)(res + base);
    float4 r1 = *(const float4*)(res + base + 4);
    float rv[8] = {r0.x, r0.y, r0.z, r0.w, r1.x, r1.y, r1.z, r1.w};
    float o[8];
    #pragma unroll
    for (int j = 0; j < 8; j++) o[j] = fmaf(acc[j], inv, rv[j]);

    if (meanout) {
        #pragma unroll
        for (int j = 0; j < 8; j++) {
            float t = o[j];
            t += __shfl_xor_sync(0xffffffffu, t, 8);
            t += __shfl_xor_sync(0xffffffffu, t, 16);
            o[j] = 0.25f * t;
        }
        if (lane < 5) {
            #pragma unroll
            for (int j = 0; j < 8; j++) {
                int d = d0 + j;
                if (d < 40) meanout[n * 40 + d] = o[j];
            }
        }
    } else {
        *(float4*)(xout + base)     = make_float4(o[0], o[1], o[2], o[3]);
        *(float4*)(xout + base + 4) = make_float4(o[4], o[5], o[6], o[7]);
    }
}

// ---------------- launch ----------------
extern "C" void kernel_launch(void* const* d_in, const int* in_sizes, int n_in,
                              void* d_out, int out_size) {
    const float* x_in  = (const float*)d_in[0];
    const int*   src   = (const int*)  d_in[1];
    const int*   dst   = (const int*)  d_in[2];
    const float* w_s0  = (const float*)d_in[3];  const float* b_s0 = (const float*)d_in[4];
    const float* w_d0  = (const float*)d_in[5];  const float* b_d0 = (const float*)d_in[6];
    const float* attn0 = (const float*)d_in[7];
    const float* w_r0  = (const float*)d_in[8];  const float* b_r0 = (const float*)d_in[9];
    const float* w_s1  = (const float*)d_in[10]; const float* b_s1 = (const float*)d_in[11];
    const float* w_d1  = (const float*)d_in[12]; const float* b_d1 = (const float*)d_in[13];
    const float* attn1 = (const float*)d_in[14];
    const float* w_s2  = (const float*)d_in[15]; const float* b_s2 = (const float*)d_in[16];
    const float* w_d2  = (const float*)d_in[17]; const float* b_d2 = (const float*)d_in[18];
    const float* attn2 = (const float*)d_in[19];
    const float* w_r2  = (const float*)d_in[20]; const float* b_r2 = (const float*)d_in[21];

    void *p;
    cudaGetSymbolAddress(&p, g_hs);     float* hs   = (float*)p;
    cudaGetSymbolAddress(&p, g_hd);     float* hd   = (float*)p;
    cudaGetSymbolAddress(&p, g_res);    float* res  = (float*)p;
    cudaGetSymbolAddress(&p, g_xa);     float* xa   = (float*)p;
    cudaGetSymbolAddress(&p, g_xb);     float* xb   = (float*)p;
    cudaGetSymbolAddress(&p, g_cnt);    int*   cnt  = (int*)p;
    cudaGetSymbolAddress(&p, g_rowptr); int*   rp   = (int*)p;
    cudaGetSymbolAddress(&p, g_wp);     int*   wp   = (int*)p;
    cudaGetSymbolAddress(&p, g_csrsrc); int*   csrs = (int*)p;
    cudaGetSymbolAddress(&p, g_wcat0);  float* wc0  = (float*)p;
    cudaGetSymbolAddress(&p, g_bcat0);  float* bc0  = (float*)p;
    cudaGetSymbolAddress(&p, g_wcat1);  float* wc1  = (float*)p;
    cudaGetSymbolAddress(&p, g_bcat1);  float* bc1  = (float*)p;
    cudaGetSymbolAddress(&p, g_wcat2);  float* wc2  = (float*)p;
    cudaGetSymbolAddress(&p, g_bcat2);  float* bc2  = (float*)p;

    const int SMEM = NSTAGE * STAGE_FLOATS * 4;    // 107520 B
    cudaFuncSetAttribute(k_mma, cudaFuncAttributeMaxDynamicSharedMemorySize, SMEM);

    const int edgeBlocks = (NN * 32 + 255) / 256;
    const int mRows = (NN + BM - 1) / BM;   // 391

    // weights first, then mma0 at submission index 3 (ncu -s 5 capture slot)
    k_catcvt<<<(128 * 768 + 768 + 255) / 256, 256>>>(w_s0, w_d0, w_r0, b_s0, b_d0, b_r0,
                                                     wc0, bc0, 128, 256, 3);
    k_catcvt<<<(256 * 512 + 512 + 255) / 256, 256>>>(w_s1, w_d1, w_d1, b_s1, b_d1, b_d1,
                                                     wc1, bc1, 256, 256, 2);
    k_catcvt<<<(256 * 480 + 480 + 255) / 256, 256>>>(w_s2, w_d2, w_r2, b_s2, b_d2, b_r2,
                                                     wc2, bc2, 256, 160, 3);

    // layer 0 GEMM: K=128, fused N=768 (hs|hd|res)
    k_mma<<<dim3(6, mRows), 256, SMEM>>>(x_in, wc0, bc0, hs, hd, res, NN, 128, 768, 256, 0);

    // CSR build (by dst)
    k_zero_cnt<<<(NN + 255) / 256, 256>>>(cnt);
    k_count   <<<(EE + 255) / 256, 256>>>(dst, cnt);
    k_scan    <<<1, 1024>>>(cnt, rp, wp);
    k_scatter <<<(EE + 255) / 256, 256>>>(src, dst, wp, csrs);

    k_edge<<<edgeBlocks, 256>>>(hs, hd, res, attn0, 64, rp, csrs, xa, (float*)0);

    // layer 1: K=256, fused N=512 (hs|hd), identity residual = xa
    k_mma<<<dim3(4, mRows), 256, SMEM>>>(xa, wc1, bc1, hs, hd, hd, NN, 256, 512, 256, 0);
    k_edge<<<edgeBlocks, 256>>>(hs, hd, xa, attn1, 64, rp, csrs, xb, (float*)0);

    // layer 2: K=256, fused N=480 (hs|hd|res), D=40 padded to 64 via remap; fused mean
    k_mma<<<dim3(4, mRows), 256, SMEM>>>(xb, wc2, bc2, hs, hd, res, NN, 256, 480, 160, 1);
    k_edge<<<edgeBlocks, 256>>>(hs, hd, res, attn2, 40, rp, csrs, (float*)0, (float*)d_out);
}